// round 15
// baseline (speedup 1.0000x reference)
#include <cuda_runtime.h>

#define NN 100000
#define EE 1600000
#define LL 4
#define BNE 1e-5f
#define NT1 1563  // ceil(NN/64)
#define NTC 3125  // ceil(NN/32)
#define PGRID 444

typedef unsigned long long ull;
typedef ulonglong2 ullv2;

// ---------------- static device scratch ----------------
__device__ float g_h[(size_t)NN * 64];
__device__ float g_hi[(size_t)NN * 64];
__device__ float g_aggr[(size_t)NN * 64];
__device__ float g_z1[(size_t)NN * 64];
__device__ float g_y1[(size_t)NN * 128];
__device__ float g_stats[1280];

__device__ __forceinline__ float lrelu(float v) { return v > 0.f ? v : 0.01f * v; }

__device__ __forceinline__ void ffma2(ull& acc, ull a, ull b) {
    asm("fma.rn.f32x2 %0, %1, %2, %0;" : "+l"(acc) : "l"(a), "l"(b));
}
__device__ __forceinline__ ull packf2(float lo, float hi) {
    union { float2 f; ull u; } t; t.f = make_float2(lo, hi); return t.u;
}
__device__ __forceinline__ float2 unpackf2(ull v) {
    union { float2 f; ull u; } t; t.u = v; return t.f;
}

// ---------------- zero stats ----------------
__global__ void k_zero() {
    int i = blockIdx.x * 256 + threadIdx.x;
    if (i < 1280) g_stats[i] = 0.f;
}

// ---------------- column stats (sum, sumsq) ----------------
template <int C>
__global__ void __launch_bounds__(256) k_stats(const float* __restrict__ src, int off) {
    const int RPI = 256 / C;
    int tid = threadIdx.x;
    int c = tid % C;
    int rg = tid / C;
    float s = 0.f, q = 0.f;
    for (int r = blockIdx.x * RPI + rg; r < NN; r += gridDim.x * RPI) {
        float v = src[(size_t)r * C + c];
        s += v; q += v * v;
    }
    __shared__ float sm[256], sq[256];
    sm[tid] = s; sq[tid] = q;
    __syncthreads();
    if (tid < C) {
#pragma unroll
        for (int g2 = 1; g2 < RPI; ++g2) { s += sm[tid + g2 * C]; q += sq[tid + g2 * C]; }
        atomicAdd(&g_stats[off + tid], s);
        atomicAdd(&g_stats[off + C + tid], q);
    }
}

// ---------------- pre-BN (+optional leaky) -> g_hi ; zero g_aggr ----------------
__global__ void __launch_bounds__(256) k_bn_pre(const float* __restrict__ in, int off,
                                                const float* __restrict__ w,
                                                const float* __restrict__ b, int leaky) {
    __shared__ float sScl[64], sShf[64];
    int tid = threadIdx.x;
    if (tid < 64) {
        float mean = g_stats[off + tid] * (1.f / NN);
        float var = g_stats[off + 64 + tid] * (1.f / NN) - mean * mean;
        float scl = w[tid] * rsqrtf(var + BNE);
        sScl[tid] = scl;
        sShf[tid] = b[tid] - mean * scl;
    }
    __syncthreads();
    int idx = blockIdx.x * 256 + tid;  // over NN*16 float4s (exact)
    float4 v = ((const float4*)in)[idx];
    int c = (idx & 15) * 4;
    float4 o;
    o.x = fmaf(v.x, sScl[c + 0], sShf[c + 0]);
    o.y = fmaf(v.y, sScl[c + 1], sShf[c + 1]);
    o.z = fmaf(v.z, sScl[c + 2], sShf[c + 2]);
    o.w = fmaf(v.w, sScl[c + 3], sShf[c + 3]);
    if (leaky) { o.x = lrelu(o.x); o.y = lrelu(o.y); o.z = lrelu(o.z); o.w = lrelu(o.w); }
    ((float4*)g_hi)[idx] = o;
    ((float4*)g_aggr)[idx] = make_float4(0.f, 0.f, 0.f, 0.f);
}

// ---------------- edge kernel: double-buffered staging (R13, best) ----------
__global__ void __launch_bounds__(256, 3) k_edge(const int* __restrict__ src,
                                                 const int* __restrict__ dst,
                                                 const float4* __restrict__ ea4,
                                                 const float* __restrict__ W,
                                                 const float* __restrict__ B) {
    __shared__ __align__(16) float sEA[2][64 * 20];
    __shared__ int sSrc[2][64], sDst[2][64];
    int tid = threadIdx.x;
    int lane = tid & 31, warp = tid >> 5;
    int d0 = lane * 2;
    ull wk0[8], wk1[8];
    const ull* Wp = (const ull*)W;
#pragma unroll
    for (int kp = 0; kp < 8; ++kp) {
        wk0[kp] = __ldg(Wp + d0 * 8 + kp);
        wk1[kp] = __ldg(Wp + d0 * 8 + 8 + kp);
    }
    float b0 = __ldg(B + d0), b1 = __ldg(B + d0 + 1);
    const float2* hi2 = (const float2*)g_hi;
    int eTile = tid >> 2, q = tid & 3;
    const int NT = EE / 64;
    const int stride = gridDim.x;
    int t0 = blockIdx.x;
    {
        int tb = t0 * 64;
        *(float4*)(&sEA[0][eTile * 20 + q * 4]) =
            __ldg(ea4 + (size_t)(tb + eTile) * 4 + q);
        if (tid < 64) sSrc[0][tid] = __ldg(src + tb + tid);
        else if (tid < 128) sDst[0][tid - 64] = __ldg(dst + tb + tid - 64);
    }
    __syncthreads();
    int p = 0;
    for (int t = t0; t < NT; t += stride, p ^= 1) {
        int tn = t + stride;
        if (tn < NT) {
            int tb = tn * 64;
            *(float4*)(&sEA[p ^ 1][eTile * 20 + q * 4]) =
                __ldg(ea4 + (size_t)(tb + eTile) * 4 + q);
            if (tid < 64) sSrc[p ^ 1][tid] = __ldg(src + tb + tid);
            else if (tid < 128) sDst[p ^ 1][tid - 64] = __ldg(dst + tb + tid - 64);
        }
        int e0 = warp * 8;
        float2 g[8];
#pragma unroll
        for (int j = 0; j < 8; ++j)
            g[j] = __ldg(hi2 + (size_t)sSrc[p][e0 + j] * 32 + lane);
#pragma unroll
        for (int j = 0; j < 8; ++j) {
            const ullv2* ep = (const ullv2*)(&sEA[p][(e0 + j) * 20]);
            ull acc0 = packf2(b0, 0.f), acc1 = packf2(b1, 0.f);
#pragma unroll
            for (int i = 0; i < 4; ++i) {
                ullv2 pr = ep[i];
                ffma2(acc0, pr.x, wk0[2 * i]);
                ffma2(acc1, pr.x, wk1[2 * i]);
                ffma2(acc0, pr.y, wk0[2 * i + 1]);
                ffma2(acc1, pr.y, wk1[2 * i + 1]);
            }
            float2 a0 = unpackf2(acc0), a1 = unpackf2(acc1);
            float m0 = fmaxf(g[j].x + a0.x + a0.y, 0.f);
            float m1 = fmaxf(g[j].y + a1.x + a1.y, 0.f);
            float* pp = g_aggr + (size_t)sDst[p][e0 + j] * 64 + d0;
            asm volatile("red.global.add.v2.f32 [%0], {%1, %2};" ::"l"(pp), "f"(m0),
                         "f"(m1) : "memory");
        }
        __syncthreads();
    }
}

// ---- k-pair FFMA2 GEMM inner: 16 outputs, 32 k-pairs, input from SINP ----
#define GEMM_KP(OUTS, SINP)                                               \
    ull acc2[16];                                                         \
    _Pragma("unroll")                                                     \
    for (int c = 0; c < 16; ++c) acc2[c] = packf2(sB[g * 16 + c], 0.f);   \
    _Pragma("unroll 4")                                                   \
    for (int kp = 0; kp < 32; ++kp) {                                     \
        ull a2 = *(const ull*)((SINP) + r * 66 + 2 * kp);                 \
        const ullv2* wp = (const ullv2*)(sW2 + kp * OUTS + g * 16);       \
        _Pragma("unroll")                                                 \
        for (int i = 0; i < 8; ++i) {                                     \
            ullv2 w = wp[i];                                              \
            ffma2(acc2[2 * i], a2, w.x);                                  \
            ffma2(acc2[2 * i + 1], a2, w.y);                              \
        }                                                                 \
    }                                                                     \
    float acc[16];                                                        \
    _Pragma("unroll")                                                     \
    for (int c = 0; c < 16; ++c) {                                        \
        float2 t2 = unpackf2(acc2[c]);                                    \
        acc[c] = t2.x + t2.y;                                             \
    }

// stats epilogue over block outputs staged in SINP (64 rows x 64 cols, stride 66)
#define STATS_EPILOGUE(soff, SINP)                                                   \
    {                                                                                \
        int col = tid & 63, grp = tid >> 6;                                          \
        float s = 0.f, q = 0.f;                                                      \
        _Pragma("unroll")                                                            \
        for (int rr = grp * 16; rr < grp * 16 + 16; ++rr) {                          \
            float v = (SINP)[rr * 66 + col];                                         \
            s += v; q += v * v;                                                      \
        }                                                                            \
        sS[tid] = s; sQ[tid] = q;                                                    \
        __syncthreads();                                                             \
        if (tid < 64) {                                                              \
            float ts = sS[tid] + sS[tid + 64] + sS[tid + 128] + sS[tid + 192];       \
            float tq = sQ[tid] + sQ[tid + 64] + sQ[tid + 128] + sQ[tid + 192];       \
            atomicAdd(&g_stats[(soff) + tid], ts);                                   \
            atomicAdd(&g_stats[(soff) + 64 + tid], tq);                              \
        }                                                                            \
    }

// ---------------- lin1 (persistent, double-buffered): z1 = ((1+eps)*hi + aggr) @ W^T + b ----
__global__ void __launch_bounds__(256, 3) k_lin1(const float* __restrict__ W,
                                                 const float* __restrict__ B,
                                                 const float* __restrict__ eps, int layer,
                                                 int soff) {
    __shared__ __align__(16) float sIn[2][64 * 66];
    __shared__ ull sW2[32 * 64];
    __shared__ float sB[64];
    __shared__ float sS[256], sQ[256];
    int tid = threadIdx.x;
    float* sWf = (float*)sW2;
#pragma unroll
    for (int j = 0; j < 16; ++j) {
        int idx = tid + j * 256;
        int c = idx >> 6, k = idx & 63;
        sWf[((k >> 1) * 64 + c) * 2 + (k & 1)] = W[idx];
    }
    if (tid < 64) sB[tid] = B[tid];
    float ep = 1.f + __ldg(eps + layer);
    const float4* hi4 = (const float4*)g_hi;
    const float4* ag4 = (const float4*)g_aggr;
    int r = tid & 63, g = tid >> 6;
#define L1_STAGE(TT, BUF)                                                       \
    {                                                                           \
        int base_ = (TT)*64;                                                    \
        int cnt_ = min(64, NN - base_);                                         \
        _Pragma("unroll")                                                       \
        for (int j = 0; j < 4; ++j) {                                           \
            int f4 = tid + j * 256;                                             \
            int rr = f4 >> 4, cc = (f4 & 15) * 4;                               \
            if (rr < cnt_) {                                                    \
                float4 a = hi4[(size_t)(base_ + rr) * 16 + (f4 & 15)];          \
                float4 gg = ag4[(size_t)(base_ + rr) * 16 + (f4 & 15)];         \
                (BUF)[rr * 66 + cc + 0] = fmaf(a.x, ep, gg.x);                  \
                (BUF)[rr * 66 + cc + 1] = fmaf(a.y, ep, gg.y);                  \
                (BUF)[rr * 66 + cc + 2] = fmaf(a.z, ep, gg.z);                  \
                (BUF)[rr * 66 + cc + 3] = fmaf(a.w, ep, gg.w);                  \
            }                                                                   \
        }                                                                       \
    }
    L1_STAGE(blockIdx.x, sIn[0])
    __syncthreads();
    int p = 0;
    for (int t = blockIdx.x; t < NT1; t += gridDim.x, p ^= 1) {
        int tn = t + gridDim.x;
        if (tn < NT1) L1_STAGE(tn, sIn[p ^ 1])
        int base = t * 64;
        int cnt = min(64, NN - base);
        bool act = r < cnt;
        GEMM_KP(64, sIn[p])
        if (act) {
            float4* o = (float4*)(g_z1 + (size_t)(base + r) * 64 + g * 16);
            o[0] = make_float4(acc[0], acc[1], acc[2], acc[3]);
            o[1] = make_float4(acc[4], acc[5], acc[6], acc[7]);
            o[2] = make_float4(acc[8], acc[9], acc[10], acc[11]);
            o[3] = make_float4(acc[12], acc[13], acc[14], acc[15]);
        }
        __syncthreads();
#pragma unroll
        for (int c = 0; c < 16; ++c) sIn[p][r * 66 + g * 16 + c] = act ? acc[c] : 0.f;
        __syncthreads();
        STATS_EPILOGUE(soff, sIn[p])
        __syncthreads();
    }
}

// ---------------- lin2 (persistent, double-buffered): h = [h +] (leaky(bn(z1)) @ W^T + b) ----
__global__ void __launch_bounds__(256, 3) k_lin2(int statin, const float* __restrict__ bnw,
                                                 const float* __restrict__ bnb,
                                                 const float* __restrict__ W,
                                                 const float* __restrict__ B, int residual,
                                                 int statout) {
    __shared__ __align__(16) float sIn[2][64 * 66];
    __shared__ ull sW2[32 * 64];
    __shared__ float sB[64], sScl[64], sShf[64];
    __shared__ float sS[256], sQ[256];
    int tid = threadIdx.x;
    float* sWf = (float*)sW2;
#pragma unroll
    for (int j = 0; j < 16; ++j) {
        int idx = tid + j * 256;
        int c = idx >> 6, k = idx & 63;
        sWf[((k >> 1) * 64 + c) * 2 + (k & 1)] = W[idx];
    }
    if (tid < 64) {
        sB[tid] = B[tid];
        float mean = g_stats[statin + tid] * (1.f / NN);
        float var = g_stats[statin + 64 + tid] * (1.f / NN) - mean * mean;
        float scl = bnw[tid] * rsqrtf(var + BNE);
        sScl[tid] = scl;
        sShf[tid] = bnb[tid] - mean * scl;
    }
    const float4* z4 = (const float4*)g_z1;
    int r = tid & 63, g = tid >> 6;
    __syncthreads();  // sScl/sShf ready before staging uses them
#define L2_STAGE(TT, BUF)                                                             \
    {                                                                                 \
        int base_ = (TT)*64;                                                          \
        int cnt_ = min(64, NN - base_);                                               \
        _Pragma("unroll")                                                             \
        for (int j = 0; j < 4; ++j) {                                                 \
            int f4 = tid + j * 256;                                                   \
            int rr = f4 >> 4, cc = (f4 & 15) * 4;                                     \
            if (rr < cnt_) {                                                          \
                float4 a = z4[(size_t)(base_ + rr) * 16 + (f4 & 15)];                 \
                (BUF)[rr * 66 + cc + 0] = lrelu(fmaf(a.x, sScl[cc + 0], sShf[cc + 0]));\
                (BUF)[rr * 66 + cc + 1] = lrelu(fmaf(a.y, sScl[cc + 1], sShf[cc + 1]));\
                (BUF)[rr * 66 + cc + 2] = lrelu(fmaf(a.z, sScl[cc + 2], sShf[cc + 2]));\
                (BUF)[rr * 66 + cc + 3] = lrelu(fmaf(a.w, sScl[cc + 3], sShf[cc + 3]));\
            }                                                                         \
        }                                                                             \
    }
    L2_STAGE(blockIdx.x, sIn[0])
    __syncthreads();
    int p = 0;
    for (int t = blockIdx.x; t < NT1; t += gridDim.x, p ^= 1) {
        int tn = t + gridDim.x;
        if (tn < NT1) L2_STAGE(tn, sIn[p ^ 1])
        int base = t * 64;
        int cnt = min(64, NN - base);
        bool act = r < cnt;
        GEMM_KP(64, sIn[p])
        if (act) {
            float4* o = (float4*)(g_h + (size_t)(base + r) * 64 + g * 16);
            if (residual) {
                float4 h0 = o[0], h1 = o[1], h2 = o[2], h3 = o[3];
                acc[0] += h0.x; acc[1] += h0.y; acc[2] += h0.z; acc[3] += h0.w;
                acc[4] += h1.x; acc[5] += h1.y; acc[6] += h1.z; acc[7] += h1.w;
                acc[8] += h2.x; acc[9] += h2.y; acc[10] += h2.z; acc[11] += h2.w;
                acc[12] += h3.x; acc[13] += h3.y; acc[14] += h3.z; acc[15] += h3.w;
            }
            o[0] = make_float4(acc[0], acc[1], acc[2], acc[3]);
            o[1] = make_float4(acc[4], acc[5], acc[6], acc[7]);
            o[2] = make_float4(acc[8], acc[9], acc[10], acc[11]);
            o[3] = make_float4(acc[12], acc[13], acc[14], acc[15]);
        }
        if (statout >= 0) {
            __syncthreads();
#pragma unroll
            for (int c = 0; c < 16; ++c) sIn[p][r * 66 + g * 16 + c] = act ? acc[c] : 0.f;
            __syncthreads();
            STATS_EPILOGUE(statout, sIn[p])
        }
        __syncthreads();
    }
}

// ---------------- cls1 (persistent, double-buffered): y1 = h @ W^T + b  (64 -> 128) ----
__global__ void __launch_bounds__(256, 3) k_cls1(const float* __restrict__ W,
                                                 const float* __restrict__ B) {
    __shared__ __align__(16) float sIn[2][32 * 66];
    __shared__ ull sW2[32 * 128];
    __shared__ float sB[128];
    int tid = threadIdx.x;
    float* sWf = (float*)sW2;
#pragma unroll
    for (int j = 0; j < 32; ++j) {
        int idx = tid + j * 256;
        int c = idx >> 6, k = idx & 63;
        sWf[((k >> 1) * 128 + c) * 2 + (k & 1)] = W[idx];
    }
    if (tid < 128) sB[tid] = B[tid];
    const float4* h4 = (const float4*)g_h;
    int r = tid & 31, g = tid >> 5;
#define C1_STAGE(TT, BUF)                                                \
    {                                                                    \
        int base_ = (TT)*32;                                             \
        int cnt_ = min(32, NN - base_);                                  \
        _Pragma("unroll")                                                \
        for (int j = 0; j < 2; ++j) {                                    \
            int f4 = tid + j * 256;                                      \
            int rr = f4 >> 4, cc = (f4 & 15) * 4;                        \
            if (rr < cnt_) {                                             \
                float4 a = h4[(size_t)(base_ + rr) * 16 + (f4 & 15)];    \
                (BUF)[rr * 66 + cc + 0] = a.x;                           \
                (BUF)[rr * 66 + cc + 1] = a.y;                           \
                (BUF)[rr * 66 + cc + 2] = a.z;                           \
                (BUF)[rr * 66 + cc + 3] = a.w;                           \
            }                                                            \
        }                                                                \
    }
    C1_STAGE(blockIdx.x, sIn[0])
    __syncthreads();
    int p = 0;
    for (int t = blockIdx.x; t < NTC; t += gridDim.x, p ^= 1) {
        int tn = t + gridDim.x;
        if (tn < NTC) C1_STAGE(tn, sIn[p ^ 1])
        int base = t * 32;
        int cnt = min(32, NN - base);
        if (r < cnt) {
            GEMM_KP(128, sIn[p])
            float4* o = (float4*)(g_y1 + (size_t)(base + r) * 128 + g * 16);
            o[0] = make_float4(acc[0], acc[1], acc[2], acc[3]);
            o[1] = make_float4(acc[4], acc[5], acc[6], acc[7]);
            o[2] = make_float4(acc[8], acc[9], acc[10], acc[11]);
            o[3] = make_float4(acc[12], acc[13], acc[14], acc[15]);
        }
        __syncthreads();
    }
}

// ---------------- cls2: out = leaky(bn(y1)) @ w2 + b2 ----------------
__global__ void __launch_bounds__(256) k_cls2(int off, const float* __restrict__ bnw,
                                              const float* __restrict__ bnb,
                                              const float* __restrict__ w2,
                                              const float* __restrict__ b2,
                                              float* __restrict__ out) {
    __shared__ float sScl[128], sShf[128], sW[128];
    int tid = threadIdx.x;
    if (tid < 128) {
        float mean = g_stats[off + tid] * (1.f / NN);
        float var = g_stats[off + 128 + tid] * (1.f / NN) - mean * mean;
        float scl = bnw[tid] * rsqrtf(var + BNE);
        sScl[tid] = scl;
        sShf[tid] = bnb[tid] - mean * scl;
        sW[tid] = w2[tid];
    }
    __syncthreads();
    int n = blockIdx.x * 256 + tid;
    if (n >= NN) return;
    const float4* row = (const float4*)(g_y1 + (size_t)n * 128);
    float acc = 0.f;
#pragma unroll 8
    for (int m4 = 0; m4 < 32; ++m4) {
        float4 v = row[m4];
        int m = m4 * 4;
        acc += lrelu(fmaf(v.x, sScl[m + 0], sShf[m + 0])) * sW[m + 0];
        acc += lrelu(fmaf(v.y, sScl[m + 1], sShf[m + 1])) * sW[m + 1];
        acc += lrelu(fmaf(v.z, sScl[m + 2], sShf[m + 2])) * sW[m + 2];
        acc += lrelu(fmaf(v.w, sScl[m + 3], sShf[m + 3])) * sW[m + 3];
    }
    out[n] = acc + __ldg(b2);
}

// ---------------- launcher ----------------
extern "C" void kernel_launch(void* const* d_in, const int* in_sizes, int n_in,
                              void* d_out, int out_size) {
    const float* x = (const float*)d_in[0];
    const int* ei = (const int*)d_in[1];
    const float* ea = (const float*)d_in[2];
    const float* bn_pre_w = (const float*)d_in[3];
    const float* bn_pre_b = (const float*)d_in[4];
    const float* edge_lin_w = (const float*)d_in[5];
    const float* edge_lin_b = (const float*)d_in[6];
    const float* lin1_w = (const float*)d_in[7];
    const float* lin1_b = (const float*)d_in[8];
    const float* bn_mid_w = (const float*)d_in[9];
    const float* bn_mid_b = (const float*)d_in[10];
    const float* lin2_w = (const float*)d_in[11];
    const float* lin2_b = (const float*)d_in[12];
    const float* eps = (const float*)d_in[13];
    const float* cls1_w = (const float*)d_in[14];
    const float* cls1_b = (const float*)d_in[15];
    const float* cls_bn_w = (const float*)d_in[16];
    const float* cls_bn_b = (const float*)d_in[17];
    const float* cls2_w = (const float*)d_in[18];
    const float* cls2_b = (const float*)d_in[19];
    float* out = (float*)d_out;
    const int* srcp = ei;
    const int* dstp = ei + EE;

    float *hP, *y1P;
    cudaGetSymbolAddress((void**)&hP, g_h);
    cudaGetSymbolAddress((void**)&y1P, g_y1);

    k_zero<<<5, 256>>>();
    k_stats<64><<<512, 256>>>(x, 0);
    for (int i = 0; i < LL; ++i) {
        const float* hin = (i == 0) ? x : hP;
        k_bn_pre<<<6250, 256>>>(hin, i * 128, bn_pre_w + i * 64, bn_pre_b + i * 64, i > 0);
        k_edge<<<1250, 256>>>(srcp, dstp, (const float4*)ea, edge_lin_w + i * 1024,
                              edge_lin_b + i * 64);
        k_lin1<<<PGRID, 256>>>(lin1_w + i * 4096, lin1_b + i * 64, eps, i, 512 + i * 128);
        k_lin2<<<PGRID, 256>>>(512 + i * 128, bn_mid_w + i * 64, bn_mid_b + i * 64,
                               lin2_w + i * 4096, lin2_b + i * 64, i > 0,
                               (i < 3) ? (i + 1) * 128 : -1);
    }
    k_cls1<<<PGRID, 256>>>(cls1_w, cls1_b);
    k_stats<128><<<512, 256>>>(y1P, 1024);
    k_cls2<<<391, 256>>>(1024, cls_bn_w, cls_bn_b, cls2_w, cls2_b, out);
}

// round 16
// speedup vs baseline: 1.0759x; 1.0759x over previous
#include <cuda_runtime.h>

#define NN 100000
#define EE 1600000
#define LL 4
#define BNE 1e-5f
#define NT1 1563  // ceil(NN/64)
#define NTC 3125  // ceil(NN/32)
#define PGRID 444

typedef unsigned long long ull;
typedef ulonglong2 ullv2;

// ---------------- static device scratch ----------------
__device__ float g_h[(size_t)NN * 64];
__device__ float g_hi[(size_t)NN * 64];
__device__ float g_aggr[(size_t)NN * 64];
__device__ float g_z1[(size_t)NN * 64];
__device__ float g_y1[(size_t)NN * 128];
__device__ float g_stats[1280];

__device__ __forceinline__ float lrelu(float v) { return v > 0.f ? v : 0.01f * v; }

__device__ __forceinline__ void ffma2(ull& acc, ull a, ull b) {
    asm("fma.rn.f32x2 %0, %1, %2, %0;" : "+l"(acc) : "l"(a), "l"(b));
}
__device__ __forceinline__ ull packf2(float lo, float hi) {
    union { float2 f; ull u; } t; t.f = make_float2(lo, hi); return t.u;
}
__device__ __forceinline__ float2 unpackf2(ull v) {
    union { float2 f; ull u; } t; t.u = v; return t.f;
}

// ---------------- zero stats ----------------
__global__ void k_zero() {
    int i = blockIdx.x * 256 + threadIdx.x;
    if (i < 1280) g_stats[i] = 0.f;
}

// ---------------- column stats (sum, sumsq) ----------------
template <int C>
__global__ void __launch_bounds__(256) k_stats(const float* __restrict__ src, int off) {
    const int RPI = 256 / C;
    int tid = threadIdx.x;
    int c = tid % C;
    int rg = tid / C;
    float s = 0.f, q = 0.f;
    for (int r = blockIdx.x * RPI + rg; r < NN; r += gridDim.x * RPI) {
        float v = src[(size_t)r * C + c];
        s += v; q += v * v;
    }
    __shared__ float sm[256], sq[256];
    sm[tid] = s; sq[tid] = q;
    __syncthreads();
    if (tid < C) {
#pragma unroll
        for (int g2 = 1; g2 < RPI; ++g2) { s += sm[tid + g2 * C]; q += sq[tid + g2 * C]; }
        atomicAdd(&g_stats[off + tid], s);
        atomicAdd(&g_stats[off + C + tid], q);
    }
}

// ---------------- pre-BN (+optional leaky) -> g_hi ; zero g_aggr ----------------
__global__ void __launch_bounds__(256) k_bn_pre(const float* __restrict__ in, int off,
                                                const float* __restrict__ w,
                                                const float* __restrict__ b, int leaky) {
    __shared__ float sScl[64], sShf[64];
    int tid = threadIdx.x;
    if (tid < 64) {
        float mean = g_stats[off + tid] * (1.f / NN);
        float var = g_stats[off + 64 + tid] * (1.f / NN) - mean * mean;
        float scl = w[tid] * rsqrtf(var + BNE);
        sScl[tid] = scl;
        sShf[tid] = b[tid] - mean * scl;
    }
    __syncthreads();
    int idx = blockIdx.x * 256 + tid;  // over NN*16 float4s (exact)
    float4 v = ((const float4*)in)[idx];
    int c = (idx & 15) * 4;
    float4 o;
    o.x = fmaf(v.x, sScl[c + 0], sShf[c + 0]);
    o.y = fmaf(v.y, sScl[c + 1], sShf[c + 1]);
    o.z = fmaf(v.z, sScl[c + 2], sShf[c + 2]);
    o.w = fmaf(v.w, sScl[c + 3], sShf[c + 3]);
    if (leaky) { o.x = lrelu(o.x); o.y = lrelu(o.y); o.z = lrelu(o.z); o.w = lrelu(o.w); }
    ((float4*)g_hi)[idx] = o;
    ((float4*)g_aggr)[idx] = make_float4(0.f, 0.f, 0.f, 0.f);
}

// ---------------- edge kernel: double-buffered staging (R13, best) ----------
__global__ void __launch_bounds__(256, 3) k_edge(const int* __restrict__ src,
                                                 const int* __restrict__ dst,
                                                 const float4* __restrict__ ea4,
                                                 const float* __restrict__ W,
                                                 const float* __restrict__ B) {
    __shared__ __align__(16) float sEA[2][64 * 20];
    __shared__ int sSrc[2][64], sDst[2][64];
    int tid = threadIdx.x;
    int lane = tid & 31, warp = tid >> 5;
    int d0 = lane * 2;
    ull wk0[8], wk1[8];
    const ull* Wp = (const ull*)W;
#pragma unroll
    for (int kp = 0; kp < 8; ++kp) {
        wk0[kp] = __ldg(Wp + d0 * 8 + kp);
        wk1[kp] = __ldg(Wp + d0 * 8 + 8 + kp);
    }
    float b0 = __ldg(B + d0), b1 = __ldg(B + d0 + 1);
    const float2* hi2 = (const float2*)g_hi;
    int eTile = tid >> 2, q = tid & 3;
    const int NT = EE / 64;
    const int stride = gridDim.x;
    int t0 = blockIdx.x;
    {
        int tb = t0 * 64;
        *(float4*)(&sEA[0][eTile * 20 + q * 4]) =
            __ldg(ea4 + (size_t)(tb + eTile) * 4 + q);
        if (tid < 64) sSrc[0][tid] = __ldg(src + tb + tid);
        else if (tid < 128) sDst[0][tid - 64] = __ldg(dst + tb + tid - 64);
    }
    __syncthreads();
    int p = 0;
    for (int t = t0; t < NT; t += stride, p ^= 1) {
        int tn = t + stride;
        if (tn < NT) {
            int tb = tn * 64;
            *(float4*)(&sEA[p ^ 1][eTile * 20 + q * 4]) =
                __ldg(ea4 + (size_t)(tb + eTile) * 4 + q);
            if (tid < 64) sSrc[p ^ 1][tid] = __ldg(src + tb + tid);
            else if (tid < 128) sDst[p ^ 1][tid - 64] = __ldg(dst + tb + tid - 64);
        }
        int e0 = warp * 8;
        float2 g[8];
#pragma unroll
        for (int j = 0; j < 8; ++j)
            g[j] = __ldg(hi2 + (size_t)sSrc[p][e0 + j] * 32 + lane);
#pragma unroll
        for (int j = 0; j < 8; ++j) {
            const ullv2* ep = (const ullv2*)(&sEA[p][(e0 + j) * 20]);
            ull acc0 = packf2(b0, 0.f), acc1 = packf2(b1, 0.f);
#pragma unroll
            for (int i = 0; i < 4; ++i) {
                ullv2 pr = ep[i];
                ffma2(acc0, pr.x, wk0[2 * i]);
                ffma2(acc1, pr.x, wk1[2 * i]);
                ffma2(acc0, pr.y, wk0[2 * i + 1]);
                ffma2(acc1, pr.y, wk1[2 * i + 1]);
            }
            float2 a0 = unpackf2(acc0), a1 = unpackf2(acc1);
            float m0 = fmaxf(g[j].x + a0.x + a0.y, 0.f);
            float m1 = fmaxf(g[j].y + a1.x + a1.y, 0.f);
            float* pp = g_aggr + (size_t)sDst[p][e0 + j] * 64 + d0;
            asm volatile("red.global.add.v2.f32 [%0], {%1, %2};" ::"l"(pp), "f"(m0),
                         "f"(m1) : "memory");
        }
        __syncthreads();
    }
}

// ---- 2-row k-pair FFMA2 GEMM: 8 outputs x 2 rows, 32 k-pairs ----
// thread (r2, g8): rows r2, r2+ROFF; outputs g8*8 .. g8*8+7
#define GEMM_KP2(OUTS, SINP, ROFF)                                        \
    ull accA[8], accB[8];                                                 \
    _Pragma("unroll")                                                     \
    for (int c = 0; c < 8; ++c) {                                         \
        accA[c] = packf2(sB[g8 * 8 + c], 0.f);                            \
        accB[c] = accA[c];                                                \
    }                                                                     \
    _Pragma("unroll 4")                                                   \
    for (int kp = 0; kp < 32; ++kp) {                                     \
        ull a2a = *(const ull*)((SINP) + r2 * 66 + 2 * kp);               \
        ull a2b = *(const ull*)((SINP) + (r2 + ROFF) * 66 + 2 * kp);      \
        const ullv2* wp = (const ullv2*)(sW2 + kp * OUTS + g8 * 8);       \
        _Pragma("unroll")                                                 \
        for (int i = 0; i < 4; ++i) {                                     \
            ullv2 w = wp[i];                                              \
            ffma2(accA[2 * i], a2a, w.x);                                 \
            ffma2(accA[2 * i + 1], a2a, w.y);                             \
            ffma2(accB[2 * i], a2b, w.x);                                 \
            ffma2(accB[2 * i + 1], a2b, w.y);                             \
        }                                                                 \
    }                                                                     \
    float fA[8], fB[8];                                                   \
    _Pragma("unroll")                                                     \
    for (int c = 0; c < 8; ++c) {                                         \
        float2 ta = unpackf2(accA[c]);                                    \
        float2 tb = unpackf2(accB[c]);                                    \
        fA[c] = ta.x + ta.y;                                              \
        fB[c] = tb.x + tb.y;                                              \
    }

// stats epilogue over block outputs staged in SINP (64 rows x 64 cols, stride 66)
#define STATS_EPILOGUE(soff, SINP)                                                   \
    {                                                                                \
        int col = tid & 63, grp = tid >> 6;                                          \
        float s = 0.f, q = 0.f;                                                      \
        _Pragma("unroll")                                                            \
        for (int rr = grp * 16; rr < grp * 16 + 16; ++rr) {                          \
            float v = (SINP)[rr * 66 + col];                                         \
            s += v; q += v * v;                                                      \
        }                                                                            \
        sS[tid] = s; sQ[tid] = q;                                                    \
        __syncthreads();                                                             \
        if (tid < 64) {                                                              \
            float ts = sS[tid] + sS[tid + 64] + sS[tid + 128] + sS[tid + 192];       \
            float tq = sQ[tid] + sQ[tid + 64] + sQ[tid + 128] + sQ[tid + 192];       \
            atomicAdd(&g_stats[(soff) + tid], ts);                                   \
            atomicAdd(&g_stats[(soff) + 64 + tid], tq);                              \
        }                                                                            \
    }

// ---------------- lin1 (persistent, 2-row threads): z1 = ((1+eps)*hi + aggr) @ W^T + b ----
__global__ void __launch_bounds__(256) k_lin1(const float* __restrict__ W,
                                              const float* __restrict__ B,
                                              const float* __restrict__ eps, int layer,
                                              int soff) {
    __shared__ __align__(16) float sIn[64 * 66];
    __shared__ ull sW2[32 * 64];
    __shared__ float sB[64];
    __shared__ float sS[256], sQ[256];
    int tid = threadIdx.x;
    float* sWf = (float*)sW2;
#pragma unroll
    for (int j = 0; j < 16; ++j) {
        int idx = tid + j * 256;
        int c = idx >> 6, k = idx & 63;
        sWf[((k >> 1) * 64 + c) * 2 + (k & 1)] = W[idx];
    }
    if (tid < 64) sB[tid] = B[tid];
    float ep = 1.f + __ldg(eps + layer);
    const float4* hi4 = (const float4*)g_hi;
    const float4* ag4 = (const float4*)g_aggr;
    int r2 = tid & 31, g8 = tid >> 5;
    __syncthreads();
    for (int t = blockIdx.x; t < NT1; t += gridDim.x) {
        int base = t * 64;
        int cnt = min(64, NN - base);
#pragma unroll
        for (int j = 0; j < 4; ++j) {
            int f4 = tid + j * 256;
            int rr = f4 >> 4, cc = (f4 & 15) * 4;
            if (rr < cnt) {
                float4 a = hi4[(size_t)(base + rr) * 16 + (f4 & 15)];
                float4 gg = ag4[(size_t)(base + rr) * 16 + (f4 & 15)];
                sIn[rr * 66 + cc + 0] = fmaf(a.x, ep, gg.x);
                sIn[rr * 66 + cc + 1] = fmaf(a.y, ep, gg.y);
                sIn[rr * 66 + cc + 2] = fmaf(a.z, ep, gg.z);
                sIn[rr * 66 + cc + 3] = fmaf(a.w, ep, gg.w);
            }
        }
        __syncthreads();
        bool actA = r2 < cnt, actB = (r2 + 32) < cnt;
        GEMM_KP2(64, sIn, 32)
        if (actA) {
            float4* o = (float4*)(g_z1 + (size_t)(base + r2) * 64 + g8 * 8);
            o[0] = make_float4(fA[0], fA[1], fA[2], fA[3]);
            o[1] = make_float4(fA[4], fA[5], fA[6], fA[7]);
        }
        if (actB) {
            float4* o = (float4*)(g_z1 + (size_t)(base + r2 + 32) * 64 + g8 * 8);
            o[0] = make_float4(fB[0], fB[1], fB[2], fB[3]);
            o[1] = make_float4(fB[4], fB[5], fB[6], fB[7]);
        }
        __syncthreads();
#pragma unroll
        for (int c = 0; c < 8; ++c) {
            sIn[r2 * 66 + g8 * 8 + c] = actA ? fA[c] : 0.f;
            sIn[(r2 + 32) * 66 + g8 * 8 + c] = actB ? fB[c] : 0.f;
        }
        __syncthreads();
        STATS_EPILOGUE(soff, sIn)
        __syncthreads();
    }
}

// ---------------- lin2 (persistent, 2-row threads): h = [h +] (leaky(bn(z1)) @ W^T + b) ----
__global__ void __launch_bounds__(256) k_lin2(int statin, const float* __restrict__ bnw,
                                              const float* __restrict__ bnb,
                                              const float* __restrict__ W,
                                              const float* __restrict__ B, int residual,
                                              int statout) {
    __shared__ __align__(16) float sIn[64 * 66];
    __shared__ ull sW2[32 * 64];
    __shared__ float sB[64], sScl[64], sShf[64];
    __shared__ float sS[256], sQ[256];
    int tid = threadIdx.x;
    float* sWf = (float*)sW2;
#pragma unroll
    for (int j = 0; j < 16; ++j) {
        int idx = tid + j * 256;
        int c = idx >> 6, k = idx & 63;
        sWf[((k >> 1) * 64 + c) * 2 + (k & 1)] = W[idx];
    }
    if (tid < 64) {
        sB[tid] = B[tid];
        float mean = g_stats[statin + tid] * (1.f / NN);
        float var = g_stats[statin + 64 + tid] * (1.f / NN) - mean * mean;
        float scl = bnw[tid] * rsqrtf(var + BNE);
        sScl[tid] = scl;
        sShf[tid] = bnb[tid] - mean * scl;
    }
    const float4* z4 = (const float4*)g_z1;
    int r2 = tid & 31, g8 = tid >> 5;
    __syncthreads();
    for (int t = blockIdx.x; t < NT1; t += gridDim.x) {
        int base = t * 64;
        int cnt = min(64, NN - base);
#pragma unroll
        for (int j = 0; j < 4; ++j) {
            int f4 = tid + j * 256;
            int rr = f4 >> 4, cc = (f4 & 15) * 4;
            if (rr < cnt) {
                float4 a = z4[(size_t)(base + rr) * 16 + (f4 & 15)];
                sIn[rr * 66 + cc + 0] = lrelu(fmaf(a.x, sScl[cc + 0], sShf[cc + 0]));
                sIn[rr * 66 + cc + 1] = lrelu(fmaf(a.y, sScl[cc + 1], sShf[cc + 1]));
                sIn[rr * 66 + cc + 2] = lrelu(fmaf(a.z, sScl[cc + 2], sShf[cc + 2]));
                sIn[rr * 66 + cc + 3] = lrelu(fmaf(a.w, sScl[cc + 3], sShf[cc + 3]));
            }
        }
        __syncthreads();
        bool actA = r2 < cnt, actB = (r2 + 32) < cnt;
        GEMM_KP2(64, sIn, 32)
        if (actA) {
            float4* o = (float4*)(g_h + (size_t)(base + r2) * 64 + g8 * 8);
            if (residual) {
                float4 h0 = o[0], h1 = o[1];
                fA[0] += h0.x; fA[1] += h0.y; fA[2] += h0.z; fA[3] += h0.w;
                fA[4] += h1.x; fA[5] += h1.y; fA[6] += h1.z; fA[7] += h1.w;
            }
            o[0] = make_float4(fA[0], fA[1], fA[2], fA[3]);
            o[1] = make_float4(fA[4], fA[5], fA[6], fA[7]);
        }
        if (actB) {
            float4* o = (float4*)(g_h + (size_t)(base + r2 + 32) * 64 + g8 * 8);
            if (residual) {
                float4 h0 = o[0], h1 = o[1];
                fB[0] += h0.x; fB[1] += h0.y; fB[2] += h0.z; fB[3] += h0.w;
                fB[4] += h1.x; fB[5] += h1.y; fB[6] += h1.z; fB[7] += h1.w;
            }
            o[0] = make_float4(fB[0], fB[1], fB[2], fB[3]);
            o[1] = make_float4(fB[4], fB[5], fB[6], fB[7]);
        }
        if (statout >= 0) {
            __syncthreads();
#pragma unroll
            for (int c = 0; c < 8; ++c) {
                sIn[r2 * 66 + g8 * 8 + c] = actA ? fA[c] : 0.f;
                sIn[(r2 + 32) * 66 + g8 * 8 + c] = actB ? fB[c] : 0.f;
            }
            __syncthreads();
            STATS_EPILOGUE(statout, sIn)
        }
        __syncthreads();
    }
}

// ---------------- cls1 (persistent, 2-row threads): y1 = h @ W^T + b  (64 -> 128) ----
__global__ void __launch_bounds__(256) k_cls1(const float* __restrict__ W,
                                              const float* __restrict__ B) {
    __shared__ __align__(16) float sIn[32 * 66];
    __shared__ ull sW2[32 * 128];
    __shared__ float sB[128];
    int tid = threadIdx.x;
    float* sWf = (float*)sW2;
#pragma unroll
    for (int j = 0; j < 32; ++j) {
        int idx = tid + j * 256;
        int c = idx >> 6, k = idx & 63;
        sWf[((k >> 1) * 128 + c) * 2 + (k & 1)] = W[idx];
    }
    if (tid < 128) sB[tid] = B[tid];
    const float4* h4 = (const float4*)g_h;
    int r2 = tid & 15, g8 = tid >> 4;  // 16 output-groups of 8
    __syncthreads();
    for (int t = blockIdx.x; t < NTC; t += gridDim.x) {
        int base = t * 32;
        int cnt = min(32, NN - base);
#pragma unroll
        for (int j = 0; j < 2; ++j) {
            int f4 = tid + j * 256;
            int rr = f4 >> 4, cc = (f4 & 15) * 4;
            if (rr < cnt) {
                float4 a = h4[(size_t)(base + rr) * 16 + (f4 & 15)];
                sIn[rr * 66 + cc + 0] = a.x;
                sIn[rr * 66 + cc + 1] = a.y;
                sIn[rr * 66 + cc + 2] = a.z;
                sIn[rr * 66 + cc + 3] = a.w;
            }
        }
        __syncthreads();
        bool actA = r2 < cnt, actB = (r2 + 16) < cnt;
        GEMM_KP2(128, sIn, 16)
        if (actA) {
            float4* o = (float4*)(g_y1 + (size_t)(base + r2) * 128 + g8 * 8);
            o[0] = make_float4(fA[0], fA[1], fA[2], fA[3]);
            o[1] = make_float4(fA[4], fA[5], fA[6], fA[7]);
        }
        if (actB) {
            float4* o = (float4*)(g_y1 + (size_t)(base + r2 + 16) * 128 + g8 * 8);
            o[0] = make_float4(fB[0], fB[1], fB[2], fB[3]);
            o[1] = make_float4(fB[4], fB[5], fB[6], fB[7]);
        }
        __syncthreads();
    }
}

// ---------------- cls2: out = leaky(bn(y1)) @ w2 + b2 ----------------
__global__ void __launch_bounds__(256) k_cls2(int off, const float* __restrict__ bnw,
                                              const float* __restrict__ bnb,
                                              const float* __restrict__ w2,
                                              const float* __restrict__ b2,
                                              float* __restrict__ out) {
    __shared__ float sScl[128], sShf[128], sW[128];
    int tid = threadIdx.x;
    if (tid < 128) {
        float mean = g_stats[off + tid] * (1.f / NN);
        float var = g_stats[off + 128 + tid] * (1.f / NN) - mean * mean;
        float scl = bnw[tid] * rsqrtf(var + BNE);
        sScl[tid] = scl;
        sShf[tid] = bnb[tid] - mean * scl;
        sW[tid] = w2[tid];
    }
    __syncthreads();
    int n = blockIdx.x * 256 + tid;
    if (n >= NN) return;
    const float4* row = (const float4*)(g_y1 + (size_t)n * 128);
    float acc = 0.f;
#pragma unroll 8
    for (int m4 = 0; m4 < 32; ++m4) {
        float4 v = row[m4];
        int m = m4 * 4;
        acc += lrelu(fmaf(v.x, sScl[m + 0], sShf[m + 0])) * sW[m + 0];
        acc += lrelu(fmaf(v.y, sScl[m + 1], sShf[m + 1])) * sW[m + 1];
        acc += lrelu(fmaf(v.z, sScl[m + 2], sShf[m + 2])) * sW[m + 2];
        acc += lrelu(fmaf(v.w, sScl[m + 3], sShf[m + 3])) * sW[m + 3];
    }
    out[n] = acc + __ldg(b2);
}

// ---------------- launcher ----------------
extern "C" void kernel_launch(void* const* d_in, const int* in_sizes, int n_in,
                              void* d_out, int out_size) {
    const float* x = (const float*)d_in[0];
    const int* ei = (const int*)d_in[1];
    const float* ea = (const float*)d_in[2];
    const float* bn_pre_w = (const float*)d_in[3];
    const float* bn_pre_b = (const float*)d_in[4];
    const float* edge_lin_w = (const float*)d_in[5];
    const float* edge_lin_b = (const float*)d_in[6];
    const float* lin1_w = (const float*)d_in[7];
    const float* lin1_b = (const float*)d_in[8];
    const float* bn_mid_w = (const float*)d_in[9];
    const float* bn_mid_b = (const float*)d_in[10];
    const float* lin2_w = (const float*)d_in[11];
    const float* lin2_b = (const float*)d_in[12];
    const float* eps = (const float*)d_in[13];
    const float* cls1_w = (const float*)d_in[14];
    const float* cls1_b = (const float*)d_in[15];
    const float* cls_bn_w = (const float*)d_in[16];
    const float* cls_bn_b = (const float*)d_in[17];
    const float* cls2_w = (const float*)d_in[18];
    const float* cls2_b = (const float*)d_in[19];
    float* out = (float*)d_out;
    const int* srcp = ei;
    const int* dstp = ei + EE;

    float *hP, *y1P;
    cudaGetSymbolAddress((void**)&hP, g_h);
    cudaGetSymbolAddress((void**)&y1P, g_y1);

    k_zero<<<5, 256>>>();
    k_stats<64><<<512, 256>>>(x, 0);
    for (int i = 0; i < LL; ++i) {
        const float* hin = (i == 0) ? x : hP;
        k_bn_pre<<<6250, 256>>>(hin, i * 128, bn_pre_w + i * 64, bn_pre_b + i * 64, i > 0);
        k_edge<<<1250, 256>>>(srcp, dstp, (const float4*)ea, edge_lin_w + i * 1024,
                              edge_lin_b + i * 64);
        k_lin1<<<PGRID, 256>>>(lin1_w + i * 4096, lin1_b + i * 64, eps, i, 512 + i * 128);
        k_lin2<<<PGRID, 256>>>(512 + i * 128, bn_mid_w + i * 64, bn_mid_b + i * 64,
                               lin2_w + i * 4096, lin2_b + i * 64, i > 0,
                               (i < 3) ? (i + 1) * 128 : -1);
    }
    k_cls1<<<PGRID, 256>>>(cls1_w, cls1_b);
    k_stats<128><<<512, 256>>>(y1P, 1024);
    k_cls2<<<391, 256>>>(1024, cls_bn_w, cls_bn_b, cls2_w, cls2_b, out);
}